// round 11
// baseline (speedup 1.0000x reference)
#include <cuda_runtime.h>
#include <cuda_bf16.h>
#include <stdint.h>

// Problem constants (fixed by setup_inputs)
#define BB    32
#define SS    8192
#define CC    256
#define KK    64
#define NCOL  (BB * CC)      // 8192 columns
#define CH    8              // row chunks per column
#define CHROWS (SS / CH)     // 1024
#define CHCAP 48             // per-chunk candidate slots (mean 14.6, sd 3.8)
#define NSEL  256            // max bitonic size (candidates mean 117, sd 10.7)

// Threshold 2.1875: P(X>t)=0.0143 -> ~117 candidates/column.
#define THRESH 2.1875f

// Scratch (device globals — allocation-free per harness rules)
__device__ unsigned long long g_cand[(size_t)NCOL * CH * CHCAP];  // 25.2 MB
__device__ int                g_cnt[NCOL * CH];
__device__ unsigned int       g_fb_n;
__device__ int                g_fb_list[NCOL];

__device__ __forceinline__ unsigned int fkey(float f) {
    unsigned int u = __float_as_uint(f);
    return (u & 0x80000000u) ? ~u : (u | 0x80000000u);
}

// ---------------------------------------------------------------------------
// Stream kernel: grid = 32b x 16tile x 8chunk. One coalesced pass over x with
// EXPLICIT 8-deep load batching (front-issued LDGs -> MLP=8/thread) so the
// branchy filter never serializes the memory stream.
// ---------------------------------------------------------------------------
__global__ void __launch_bounds__(256) stream_kernel(const float* __restrict__ x) {
    __shared__ int scnt[16];
    const int tid = threadIdx.x;
    const int bid = blockIdx.x;
    const int h   = bid & 7;
    const int ct  = (bid >> 3) & 15;
    const int b   = bid >> 7;

    if (bid == 0 && tid == 0) g_fb_n = 0;   // whole grid finishes before select
    if (tid < 16) scnt[tid] = 0;
    __syncthreads();

    const int q  = tid & 3;                 // float4 within the 64B tile row
    const int sr = tid >> 2;                // 0..63
    const float4* __restrict__ x4 = reinterpret_cast<const float4*>(x);
    const size_t base = (size_t)b * SS * (CC / 4) + ct * 4 + q
                      + (size_t)(h * CHROWS + sr) * (CC / 4);
    const int colbase = b * CC + ct * 16 + q * 4;
    const int s0 = h * CHROWS + sr;

    for (int itb = 0; itb < 2; itb++) {
        // ---- front-batched loads (8 independent LDG.128, no branches between) ----
        float4 v[8];
#pragma unroll
        for (int g = 0; g < 8; g++)
            v[g] = __ldcs(&x4[base + (size_t)((itb * 8 + g) * 64) * (CC / 4)]);

        // ---- filter/append tail ----
#pragma unroll
        for (int g = 0; g < 8; g++) {
            float m = fmaxf(fmaxf(v[g].x, v[g].y), fmaxf(v[g].z, v[g].w));
            if (m >= THRESH) {
                const int s = s0 + (itb * 8 + g) * 64;
                float vals[4] = {v[g].x, v[g].y, v[g].z, v[g].w};
#pragma unroll
                for (int l = 0; l < 4; l++) {
                    if (vals[l] >= THRESH) {
                        const int cl = q * 4 + l;
                        int pos = atomicAdd(&scnt[cl], 1);
                        if (pos < CHCAP) {
                            unsigned int key = __float_as_uint(vals[l]) | 0x80000000u;
                            g_cand[((size_t)(colbase + l) * CH + h) * CHCAP + pos] =
                                ((unsigned long long)key << 32) | (unsigned int)s;
                        }
                    }
                }
            }
        }
    }
    __syncthreads();
    if (tid < 16)
        g_cnt[(b * CC + ct * 16 + tid) * CH + h] = scnt[tid];
}

// ---------------------------------------------------------------------------
// Select kernel: one warp per column. Compact chunk segments into smem, then
// register bitonic sort (128-wide when n<=128, ~85% of columns; else 256),
// take top-64, bitonic re-sort by original index, write out.
// ---------------------------------------------------------------------------
__global__ void __launch_bounds__(256) select_kernel(float* __restrict__ out) {
    __shared__ unsigned long long sbuf[8][NSEL];    // 16 KB

    const int tid  = threadIdx.x;
    const int w    = tid >> 5;
    const int lane = tid & 31;
    const int col  = blockIdx.x * 8 + w;
    const int b    = col >> 8;
    const int c    = col & (CC - 1);

    // counts + exclusive scan over 8 chunks (lanes 0..7)
    int cnt = (lane < CH) ? g_cnt[col * CH + lane] : 0;
    unsigned int ovf = __ballot_sync(0xffffffffu, (lane < CH) && (cnt > CHCAP));
    int sc = cnt;
#pragma unroll
    for (int d = 1; d < 8; d <<= 1) {
        int t2 = __shfl_up_sync(0xffffffffu, sc, d);
        if (lane >= d) sc += t2;
    }
    const int n = __shfl_sync(0xffffffffu, sc, CH - 1);
    const int excl = sc - cnt;

    if (n >= KK && n <= NSEL && ovf == 0u) {
        // ---- compact segments into smem ----
#pragma unroll
        for (int h = 0; h < CH; h++) {
            int chn  = __shfl_sync(0xffffffffu, cnt, h);
            int bs   = __shfl_sync(0xffffffffu, excl, h);
            const unsigned long long* src = &g_cand[((size_t)col * CH + h) * CHCAP];
            for (int i = lane; i < chn; i += 32)
                sbuf[w][bs + i] = src[i];
        }
        __syncwarp();

        unsigned long long t6, t7;   // will hold the top-64 ascending

        if (n <= 128) {
            // ======== 128-wide path (R=4), ~85% of columns ========
            unsigned long long v[4];
#pragma unroll
            for (int r = 0; r < 4; r++) {
                int e = r * 32 + lane;
                v[r] = (e < n) ? sbuf[w][e] : 0ull;
            }
#pragma unroll
            for (int k = 2; k <= 128; k <<= 1) {
#pragma unroll
                for (int j = k >> 1; j > 0; j >>= 1) {
                    if (j < 32) {
#pragma unroll
                        for (int r = 0; r < 4; r++) {
                            const int e = r * 32 + lane;
                            unsigned long long pv =
                                __shfl_xor_sync(0xffffffffu, v[r], j);
                            bool keep_min = (((e & k) == 0) == ((lane & j) == 0));
                            v[r] = ((v[r] < pv) == keep_min) ? v[r] : pv;
                        }
                    } else {
                        const int jr = j >> 5;
#pragma unroll
                        for (int r = 0; r < 4; r++) {
                            if ((r & jr) == 0) {
                                const int r2 = r | jr;
                                const int e = r * 32 + lane;
                                bool asc = ((e & k) == 0);
                                unsigned long long a = v[r], bb = v[r2];
                                if (asc ? (a > bb) : (a < bb)) { v[r] = bb; v[r2] = a; }
                            }
                        }
                    }
                }
            }
            t6 = v[2]; t7 = v[3];          // elements [64,128) = top 64
        } else {
            // ======== 256-wide path (R=8) ========
            unsigned long long v[8];
#pragma unroll
            for (int r = 0; r < 8; r++) {
                int e = r * 32 + lane;
                v[r] = (e < n) ? sbuf[w][e] : 0ull;
            }
#pragma unroll
            for (int k = 2; k <= 256; k <<= 1) {
#pragma unroll
                for (int j = k >> 1; j > 0; j >>= 1) {
                    if (j < 32) {
#pragma unroll
                        for (int r = 0; r < 8; r++) {
                            const int e = r * 32 + lane;
                            unsigned long long pv =
                                __shfl_xor_sync(0xffffffffu, v[r], j);
                            bool keep_min = (((e & k) == 0) == ((lane & j) == 0));
                            v[r] = ((v[r] < pv) == keep_min) ? v[r] : pv;
                        }
                    } else {
                        const int jr = j >> 5;
#pragma unroll
                        for (int r = 0; r < 8; r++) {
                            if ((r & jr) == 0) {
                                const int r2 = r | jr;
                                const int e = r * 32 + lane;
                                bool asc = ((e & k) == 0);
                                unsigned long long a = v[r], bb = v[r2];
                                if (asc ? (a > bb) : (a < bb)) { v[r] = bb; v[r2] = a; }
                            }
                        }
                    }
                }
            }
            t6 = v[6]; t7 = v[7];          // elements [192,256) = top 64
        }

        // ---- bitonic ascending sort of the 64 selected by low-32 (index s) ----
#pragma unroll
        for (int k = 2; k <= 64; k <<= 1) {
#pragma unroll
            for (int j = k >> 1; j > 0; j >>= 1) {
                if (j < 32) {
                    {
                        const int f = lane;                    // t6
                        unsigned long long pv = __shfl_xor_sync(0xffffffffu, t6, j);
                        bool keep_min = (((f & k) == 0) == ((lane & j) == 0));
                        bool mine_min = ((unsigned int)t6 < (unsigned int)pv);
                        t6 = (mine_min == keep_min) ? t6 : pv;
                    }
                    {
                        const int f = 32 + lane;               // t7
                        unsigned long long pv = __shfl_xor_sync(0xffffffffu, t7, j);
                        bool keep_min = (((f & k) == 0) == ((lane & j) == 0));
                        bool mine_min = ((unsigned int)t7 < (unsigned int)pv);
                        t7 = (mine_min == keep_min) ? t7 : pv;
                    }
                } else {  // j == 32 (k == 64): ascending merge across t6/t7
                    unsigned long long a = t6, bb = t7;
                    if ((unsigned int)a > (unsigned int)bb) { t6 = bb; t7 = a; }
                }
            }
        }

        // ---- write: element f -> out[b][f][c] ----
        unsigned int k6 = (unsigned int)(t6 >> 32);
        unsigned int k7 = (unsigned int)(t7 >> 32);
        out[((size_t)b * KK + lane) * CC + c]      = __uint_as_float(k6 & 0x7FFFFFFFu);
        out[((size_t)b * KK + 32 + lane) * CC + c] = __uint_as_float(k7 & 0x7FFFFFFFu);
    } else {
        if (lane == 0) {
            unsigned int i = atomicAdd(&g_fb_n, 1u);
            g_fb_list[i] = col;
        }
    }
}

// ---------------------------------------------------------------------------
// Exact fallback (expected no-op): block per flagged column; smem-cached
// column, 64-pass bitwise select on (key,s) composite + ordered scatter.
// ---------------------------------------------------------------------------
__global__ void __launch_bounds__(256) fallback_kernel(const float* __restrict__ x,
                                                       float* __restrict__ out) {
    __shared__ float scol[SS];              // 32 KB
    __shared__ int scnt[256];
    const int tid = threadIdx.x;
    const unsigned int nfb = g_fb_n;

    for (unsigned int i = blockIdx.x; i < nfb; i += gridDim.x) {
        const int col = g_fb_list[i];
        const int b = col >> 8;
        const int c = col & (CC - 1);

        for (int s = tid; s < SS; s += 256)
            scol[s] = x[((size_t)b * SS + s) * CC + c];
        __syncthreads();

        unsigned long long V = 0;
        for (int bit = 63; bit >= 0; bit--) {
            unsigned long long cand = V | (1ull << bit);
            int local = 0;
            for (int s = tid; s < SS; s += 256) {
                unsigned long long comp =
                    ((unsigned long long)fkey(scol[s]) << 32) | (unsigned int)s;
                local += (comp >= cand);
            }
            scnt[tid] = local;
            __syncthreads();
            for (int st = 128; st > 0; st >>= 1) {
                if (tid < st) scnt[tid] += scnt[tid + st];
                __syncthreads();
            }
            int cntv = scnt[0];
            __syncthreads();
            if (cntv >= KK) V = cand;
        }

        const int per = SS / 256;
        int lcnt = 0;
        for (int k2 = 0; k2 < per; k2++) {
            int s = tid * per + k2;
            unsigned long long comp =
                ((unsigned long long)fkey(scol[s]) << 32) | (unsigned int)s;
            lcnt += (comp >= V);
        }
        scnt[tid] = lcnt;
        __syncthreads();
        for (int off = 1; off < 256; off <<= 1) {
            int vv = scnt[tid];
            int ww = (tid >= off) ? scnt[tid - off] : 0;
            __syncthreads();
            scnt[tid] = vv + ww;
            __syncthreads();
        }
        int base = scnt[tid] - lcnt;
        for (int k2 = 0; k2 < per; k2++) {
            int s = tid * per + k2;
            unsigned long long comp =
                ((unsigned long long)fkey(scol[s]) << 32) | (unsigned int)s;
            if (comp >= V) {
                if (base < KK)
                    out[((size_t)b * KK + base) * CC + c] = scol[s];
                base++;
            }
        }
        __syncthreads();
    }
}

extern "C" void kernel_launch(void* const* d_in, const int* in_sizes, int n_in,
                              void* d_out, int out_size) {
    const float* x = (const float*)d_in[0];
    float* out = (float*)d_out;

    stream_kernel<<<BB * 16 * CH, 256>>>(x);     // 4096 blocks
    select_kernel<<<NCOL / 8, 256>>>(out);       // 1024 blocks
    fallback_kernel<<<16, 256>>>(x, out);
}

// round 13
// speedup vs baseline: 1.0791x; 1.0791x over previous
#include <cuda_runtime.h>
#include <cuda_bf16.h>
#include <stdint.h>

// Problem constants (fixed by setup_inputs)
#define BB    32
#define SS    8192
#define CC    256
#define KK    64
#define NCOL  (BB * CC)      // 8192 columns
#define CH    8              // row chunks per column
#define CHROWS (SS / CH)     // 1024
#define CHCAP 48             // per-chunk candidate slots (mean 14.6, sd 3.8)
#define NSEL  256            // max bitonic size (candidates mean 117, sd 10.7)

// Threshold 2.1875: P(X>t)=0.0143 -> ~117 candidates/column.
#define THRESH 2.1875f

// Scratch (device globals — allocation-free per harness rules)
__device__ unsigned long long g_cand[(size_t)NCOL * CH * CHCAP];  // 25.2 MB
__device__ int                g_cnt[NCOL * CH];

__device__ __forceinline__ unsigned int fkey(float f) {
    unsigned int u = __float_as_uint(f);
    return (u & 0x80000000u) ? ~u : (u | 0x80000000u);
}

// ---------------------------------------------------------------------------
// Stream kernel: grid = 32b x 16tile x 8chunk. One coalesced pass over x with
// 4-deep front-batched loads; launch_bounds forces 6 blocks/SM (75% occ) so
// enough warps are resident to cover DRAM latency.
// ---------------------------------------------------------------------------
__global__ void __launch_bounds__(256, 6) stream_kernel(const float* __restrict__ x) {
    __shared__ int scnt[16];
    const int tid = threadIdx.x;
    const int bid = blockIdx.x;
    const int h   = bid & 7;
    const int ct  = (bid >> 3) & 15;
    const int b   = bid >> 7;

    if (tid < 16) scnt[tid] = 0;
    __syncthreads();

    const int q  = tid & 3;                 // float4 within the 64B tile row
    const int sr = tid >> 2;                // 0..63
    const float4* __restrict__ x4 = reinterpret_cast<const float4*>(x);
    const size_t base = (size_t)b * SS * (CC / 4) + ct * 4 + q
                      + (size_t)(h * CHROWS + sr) * (CC / 4);
    const int colbase = b * CC + ct * 16 + q * 4;
    const int s0 = h * CHROWS + sr;

    for (int itb = 0; itb < 4; itb++) {
        // ---- front-batched loads (4 independent LDG.128, no branches between) ----
        float4 v[4];
#pragma unroll
        for (int g = 0; g < 4; g++)
            v[g] = __ldcs(&x4[base + (size_t)((itb * 4 + g) * 64) * (CC / 4)]);

        // ---- filter/append tail ----
#pragma unroll
        for (int g = 0; g < 4; g++) {
            float m = fmaxf(fmaxf(v[g].x, v[g].y), fmaxf(v[g].z, v[g].w));
            if (m >= THRESH) {
                const int s = s0 + (itb * 4 + g) * 64;
                float vals[4] = {v[g].x, v[g].y, v[g].z, v[g].w};
#pragma unroll
                for (int l = 0; l < 4; l++) {
                    if (vals[l] >= THRESH) {
                        const int cl = q * 4 + l;
                        int pos = atomicAdd(&scnt[cl], 1);
                        if (pos < CHCAP) {
                            unsigned int key = __float_as_uint(vals[l]) | 0x80000000u;
                            g_cand[((size_t)(colbase + l) * CH + h) * CHCAP + pos] =
                                ((unsigned long long)key << 32) | (unsigned int)s;
                        }
                    }
                }
            }
        }
    }
    __syncthreads();
    if (tid < 16)
        g_cnt[(b * CC + ct * 16 + tid) * CH + h] = scnt[tid];
}

// ---------------------------------------------------------------------------
// Select kernel: one warp per column — compact chunk segments into smem,
// register bitonic sort (128-wide when n<=128, else 256), take top-64,
// bitonic re-sort by original index, write out.
// Pathological columns (n<64, n>256, chunk overflow — sigma>=5 events) are
// handled by a block-cooperative exact epilogue reading x directly.
// ---------------------------------------------------------------------------
__global__ void __launch_bounds__(256) select_kernel(const float* __restrict__ x,
                                                     float* __restrict__ out) {
    __shared__ unsigned long long sbuf[8][NSEL];    // 16 KB
    __shared__ int s_fail[8];
    __shared__ int s_nfail;
    __shared__ int sred[256];                       // 1 KB reduction scratch

    const int tid  = threadIdx.x;
    const int w    = tid >> 5;
    const int lane = tid & 31;
    const int col  = blockIdx.x * 8 + w;
    const int b    = col >> 8;
    const int c    = col & (CC - 1);

    if (tid == 0) s_nfail = 0;
    __syncthreads();

    // counts + exclusive scan over 8 chunks (lanes 0..7)
    int cnt = (lane < CH) ? g_cnt[col * CH + lane] : 0;
    unsigned int ovf = __ballot_sync(0xffffffffu, (lane < CH) && (cnt > CHCAP));
    int sc = cnt;
#pragma unroll
    for (int d = 1; d < 8; d <<= 1) {
        int t2 = __shfl_up_sync(0xffffffffu, sc, d);
        if (lane >= d) sc += t2;
    }
    const int n = __shfl_sync(0xffffffffu, sc, CH - 1);
    const int excl = sc - cnt;

    if (n >= KK && n <= NSEL && ovf == 0u) {
        // ---- compact segments into smem ----
#pragma unroll
        for (int h = 0; h < CH; h++) {
            int chn  = __shfl_sync(0xffffffffu, cnt, h);
            int bs   = __shfl_sync(0xffffffffu, excl, h);
            const unsigned long long* src = &g_cand[((size_t)col * CH + h) * CHCAP];
            for (int i = lane; i < chn; i += 32)
                sbuf[w][bs + i] = src[i];
        }
        __syncwarp();

        unsigned long long t6, t7;   // will hold the top-64 ascending

        if (n <= 128) {
            // ======== 128-wide path (R=4), ~85% of columns ========
            unsigned long long v[4];
#pragma unroll
            for (int r = 0; r < 4; r++) {
                int e = r * 32 + lane;
                v[r] = (e < n) ? sbuf[w][e] : 0ull;
            }
#pragma unroll
            for (int k = 2; k <= 128; k <<= 1) {
#pragma unroll
                for (int j = k >> 1; j > 0; j >>= 1) {
                    if (j < 32) {
#pragma unroll
                        for (int r = 0; r < 4; r++) {
                            const int e = r * 32 + lane;
                            unsigned long long pv =
                                __shfl_xor_sync(0xffffffffu, v[r], j);
                            bool keep_min = (((e & k) == 0) == ((lane & j) == 0));
                            v[r] = ((v[r] < pv) == keep_min) ? v[r] : pv;
                        }
                    } else {
                        const int jr = j >> 5;
#pragma unroll
                        for (int r = 0; r < 4; r++) {
                            if ((r & jr) == 0) {
                                const int r2 = r | jr;
                                const int e = r * 32 + lane;
                                bool asc = ((e & k) == 0);
                                unsigned long long a = v[r], bb = v[r2];
                                if (asc ? (a > bb) : (a < bb)) { v[r] = bb; v[r2] = a; }
                            }
                        }
                    }
                }
            }
            t6 = v[2]; t7 = v[3];          // elements [64,128) = top 64
        } else {
            // ======== 256-wide path (R=8) ========
            unsigned long long v[8];
#pragma unroll
            for (int r = 0; r < 8; r++) {
                int e = r * 32 + lane;
                v[r] = (e < n) ? sbuf[w][e] : 0ull;
            }
#pragma unroll
            for (int k = 2; k <= 256; k <<= 1) {
#pragma unroll
                for (int j = k >> 1; j > 0; j >>= 1) {
                    if (j < 32) {
#pragma unroll
                        for (int r = 0; r < 8; r++) {
                            const int e = r * 32 + lane;
                            unsigned long long pv =
                                __shfl_xor_sync(0xffffffffu, v[r], j);
                            bool keep_min = (((e & k) == 0) == ((lane & j) == 0));
                            v[r] = ((v[r] < pv) == keep_min) ? v[r] : pv;
                        }
                    } else {
                        const int jr = j >> 5;
#pragma unroll
                        for (int r = 0; r < 8; r++) {
                            if ((r & jr) == 0) {
                                const int r2 = r | jr;
                                const int e = r * 32 + lane;
                                bool asc = ((e & k) == 0);
                                unsigned long long a = v[r], bb = v[r2];
                                if (asc ? (a > bb) : (a < bb)) { v[r] = bb; v[r2] = a; }
                            }
                        }
                    }
                }
            }
            t6 = v[6]; t7 = v[7];          // elements [192,256) = top 64
        }

        // ---- bitonic ascending sort of the 64 selected by low-32 (index s) ----
#pragma unroll
        for (int k = 2; k <= 64; k <<= 1) {
#pragma unroll
            for (int j = k >> 1; j > 0; j >>= 1) {
                if (j < 32) {
                    {
                        const int f = lane;                    // t6
                        unsigned long long pv = __shfl_xor_sync(0xffffffffu, t6, j);
                        bool keep_min = (((f & k) == 0) == ((lane & j) == 0));
                        bool mine_min = ((unsigned int)t6 < (unsigned int)pv);
                        t6 = (mine_min == keep_min) ? t6 : pv;
                    }
                    {
                        const int f = 32 + lane;               // t7
                        unsigned long long pv = __shfl_xor_sync(0xffffffffu, t7, j);
                        bool keep_min = (((f & k) == 0) == ((lane & j) == 0));
                        bool mine_min = ((unsigned int)t7 < (unsigned int)pv);
                        t7 = (mine_min == keep_min) ? t7 : pv;
                    }
                } else {  // j == 32 (k == 64): ascending merge across t6/t7
                    unsigned long long a = t6, bb = t7;
                    if ((unsigned int)a > (unsigned int)bb) { t6 = bb; t7 = a; }
                }
            }
        }

        // ---- write: element f -> out[b][f][c] ----
        unsigned int k6 = (unsigned int)(t6 >> 32);
        unsigned int k7 = (unsigned int)(t7 >> 32);
        out[((size_t)b * KK + lane) * CC + c]      = __uint_as_float(k6 & 0x7FFFFFFFu);
        out[((size_t)b * KK + 32 + lane) * CC + c] = __uint_as_float(k7 & 0x7FFFFFFFu);
    } else {
        if (lane == 0) {
            int i = atomicAdd(&s_nfail, 1);
            s_fail[i] = col;
        }
    }

    // ---- block-cooperative exact epilogue (expected no-op; sigma>=5 events) ----
    __syncthreads();
    const int nf = s_nfail;
    for (int f = 0; f < nf; f++) {
        const int fcol = s_fail[f];
        const int fb = fcol >> 8;
        const int fc = fcol & (CC - 1);
        const size_t xbase = (size_t)fb * SS * CC + fc;

        // V = K-th largest 64-bit composite, built bit by bit (reads x via L2).
        unsigned long long V = 0;
        for (int bit = 63; bit >= 0; bit--) {
            unsigned long long cand = V | (1ull << bit);
            int local = 0;
            for (int s = tid; s < SS; s += 256) {
                float fv = x[xbase + (size_t)s * CC];
                unsigned long long comp =
                    ((unsigned long long)fkey(fv) << 32) | (unsigned int)s;
                local += (comp >= cand);
            }
            sred[tid] = local;
            __syncthreads();
            for (int st = 128; st > 0; st >>= 1) {
                if (tid < st) sred[tid] += sred[tid + st];
                __syncthreads();
            }
            int cntv = sred[0];
            __syncthreads();
            if (cntv >= KK) V = cand;
        }

        // Ordered write: thread t owns contiguous s-range, exclusive scan.
        const int per = SS / 256;           // 32
        int lcnt = 0;
        for (int k2 = 0; k2 < per; k2++) {
            int s = tid * per + k2;
            float fv = x[xbase + (size_t)s * CC];
            unsigned long long comp =
                ((unsigned long long)fkey(fv) << 32) | (unsigned int)s;
            lcnt += (comp >= V);
        }
        sred[tid] = lcnt;
        __syncthreads();
        for (int off = 1; off < 256; off <<= 1) {
            int vv = sred[tid];
            int ww = (tid >= off) ? sred[tid - off] : 0;
            __syncthreads();
            sred[tid] = vv + ww;
            __syncthreads();
        }
        int basep = sred[tid] - lcnt;
        for (int k2 = 0; k2 < per; k2++) {
            int s = tid * per + k2;
            float fv = x[xbase + (size_t)s * CC];
            unsigned long long comp =
                ((unsigned long long)fkey(fv) << 32) | (unsigned int)s;
            if (comp >= V) {
                if (basep < KK)
                    out[((size_t)fb * KK + basep) * CC + fc] = fv;
                basep++;
            }
        }
        __syncthreads();
    }
}

extern "C" void kernel_launch(void* const* d_in, const int* in_sizes, int n_in,
                              void* d_out, int out_size) {
    const float* x = (const float*)d_in[0];
    float* out = (float*)d_out;

    stream_kernel<<<BB * 16 * CH, 256>>>(x);     // 4096 blocks
    select_kernel<<<NCOL / 8, 256>>>(x, out);    // 1024 blocks
}

// round 14
// speedup vs baseline: 1.0832x; 1.0038x over previous
#include <cuda_runtime.h>
#include <cuda_bf16.h>
#include <stdint.h>

// Problem constants (fixed by setup_inputs)
#define BB    32
#define SS    8192
#define CC    256
#define KK    64
#define NCOL  (BB * CC)      // 8192 columns
#define CH    8              // row chunks per column
#define CHROWS (SS / CH)     // 1024
#define CHCAP 48             // per-chunk candidate slots (mean 14.6, sd 3.8)
#define NSEL  256            // max candidates (mean 117, sd 10.7)

// Threshold 2.1875: P(X>t)=0.0143 -> ~117 candidates/column.
#define THRESH 2.1875f

// Scratch (device globals — allocation-free per harness rules)
__device__ unsigned long long g_cand[(size_t)NCOL * CH * CHCAP];  // 25.2 MB
__device__ int                g_cnt[NCOL * CH];

__device__ __forceinline__ unsigned int fkey(float f) {
    unsigned int u = __float_as_uint(f);
    return (u & 0x80000000u) ? ~u : (u | 0x80000000u);
}

// ---------------------------------------------------------------------------
// Stream kernel (unchanged — measured ~45.6us at ~80% effective BW).
// ---------------------------------------------------------------------------
__global__ void __launch_bounds__(256, 6) stream_kernel(const float* __restrict__ x) {
    __shared__ int scnt[16];
    const int tid = threadIdx.x;
    const int bid = blockIdx.x;
    const int h   = bid & 7;
    const int ct  = (bid >> 3) & 15;
    const int b   = bid >> 7;

    if (tid < 16) scnt[tid] = 0;
    __syncthreads();

    const int q  = tid & 3;
    const int sr = tid >> 2;
    const float4* __restrict__ x4 = reinterpret_cast<const float4*>(x);
    const size_t base = (size_t)b * SS * (CC / 4) + ct * 4 + q
                      + (size_t)(h * CHROWS + sr) * (CC / 4);
    const int colbase = b * CC + ct * 16 + q * 4;
    const int s0 = h * CHROWS + sr;

    for (int itb = 0; itb < 4; itb++) {
        float4 v[4];
#pragma unroll
        for (int g = 0; g < 4; g++)
            v[g] = __ldcs(&x4[base + (size_t)((itb * 4 + g) * 64) * (CC / 4)]);

#pragma unroll
        for (int g = 0; g < 4; g++) {
            float m = fmaxf(fmaxf(v[g].x, v[g].y), fmaxf(v[g].z, v[g].w));
            if (m >= THRESH) {
                const int s = s0 + (itb * 4 + g) * 64;
                float vals[4] = {v[g].x, v[g].y, v[g].z, v[g].w};
#pragma unroll
                for (int l = 0; l < 4; l++) {
                    if (vals[l] >= THRESH) {
                        const int cl = q * 4 + l;
                        int pos = atomicAdd(&scnt[cl], 1);
                        if (pos < CHCAP) {
                            unsigned int key = __float_as_uint(vals[l]) | 0x80000000u;
                            g_cand[((size_t)(colbase + l) * CH + h) * CHCAP + pos] =
                                ((unsigned long long)key << 32) | (unsigned int)s;
                        }
                    }
                }
            }
        }
    }
    __syncthreads();
    if (tid < 16)
        g_cnt[(b * CC + ct * 16 + tid) * CH + h] = scnt[tid];
}

// ---------------------------------------------------------------------------
// Warp sort helpers (64-element sequences: reg lo holds e=lane, hi e=32+lane)
// ---------------------------------------------------------------------------
template <int NS>
__device__ __forceinline__ void sort64_batch(unsigned long long (&lo)[NS],
                                             unsigned long long (&hi)[NS],
                                             int lane) {
#pragma unroll
    for (int k = 2; k <= 32; k <<= 1) {
#pragma unroll
        for (int j = k >> 1; j > 0; j >>= 1) {
#pragma unroll
            for (int q = 0; q < NS; q++) {
                unsigned long long p = __shfl_xor_sync(0xffffffffu, lo[q], j);
                bool km = ((lane & k) == 0) == ((lane & j) == 0);
                lo[q] = ((lo[q] < p) == km) ? lo[q] : p;
                unsigned long long p2 = __shfl_xor_sync(0xffffffffu, hi[q], j);
                bool km2 = (((lane + 32) & k) == 0) == ((lane & j) == 0);
                hi[q] = ((hi[q] < p2) == km2) ? hi[q] : p2;
            }
        }
    }
    // k = 64: cross-reg (j=32), then ascending in-warp merge
#pragma unroll
    for (int q = 0; q < NS; q++)
        if (lo[q] > hi[q]) { unsigned long long t = lo[q]; lo[q] = hi[q]; hi[q] = t; }
#pragma unroll
    for (int j = 16; j > 0; j >>= 1) {
#pragma unroll
        for (int q = 0; q < NS; q++) {
            bool km = ((lane & j) == 0);
            unsigned long long p = __shfl_xor_sync(0xffffffffu, lo[q], j);
            lo[q] = ((lo[q] < p) == km) ? lo[q] : p;
            unsigned long long p2 = __shfl_xor_sync(0xffffffffu, hi[q], j);
            hi[q] = ((hi[q] < p2) == km) ? hi[q] : p2;
        }
    }
}

// Bitonic 64-seq -> ascending (after a half-cleaner).
__device__ __forceinline__ void bmerge64(unsigned long long& lo,
                                         unsigned long long& hi, int lane) {
    if (lo > hi) { unsigned long long t = lo; lo = hi; hi = t; }
#pragma unroll
    for (int j = 16; j > 0; j >>= 1) {
        bool km = ((lane & j) == 0);
        unsigned long long p = __shfl_xor_sync(0xffffffffu, lo, j);
        lo = ((lo < p) == km) ? lo : p;
        unsigned long long p2 = __shfl_xor_sync(0xffffffffu, hi, j);
        hi = ((hi < p2) == km) ? hi : p2;
    }
}

__device__ __forceinline__ unsigned long long max64(unsigned long long a,
                                                    unsigned long long b) {
    return a > b ? a : b;
}

// Ascending sort of a 64-seq of 32-bit tokens.
__device__ __forceinline__ void sort64_u32(unsigned int& a, unsigned int& b,
                                           int lane) {
#pragma unroll
    for (int k = 2; k <= 32; k <<= 1) {
#pragma unroll
        for (int j = k >> 1; j > 0; j >>= 1) {
            unsigned int p = __shfl_xor_sync(0xffffffffu, a, j);
            bool km = ((lane & k) == 0) == ((lane & j) == 0);
            a = ((a < p) == km) ? a : p;
            unsigned int p2 = __shfl_xor_sync(0xffffffffu, b, j);
            bool km2 = (((lane + 32) & k) == 0) == ((lane & j) == 0);
            b = ((b < p2) == km2) ? b : p2;
        }
    }
    if (a > b) { unsigned int t = a; a = b; b = t; }
#pragma unroll
    for (int j = 16; j > 0; j >>= 1) {
        bool km = ((lane & j) == 0);
        unsigned int p = __shfl_xor_sync(0xffffffffu, a, j);
        a = ((a < p) == km) ? a : p;
        unsigned int p2 = __shfl_xor_sync(0xffffffffu, b, j);
        b = ((b < p2) == km) ? b : p2;
    }
}

// ---------------------------------------------------------------------------
// Select kernel: 64 threads (2 warps), one column per warp.
// Partial top-64: sorted 64-runs + bitonic half-cleaners; index order restored
// via 32-bit (s<<7|pos) token sort + dynamic-shfl gather.
// ---------------------------------------------------------------------------
__global__ void __launch_bounds__(64) select_kernel(const float* __restrict__ x,
                                                    float* __restrict__ out) {
    __shared__ unsigned long long sbuf[2][NSEL];    // 4 KB
    __shared__ int s_fail[2];
    __shared__ int s_nfail;
    __shared__ int sred[64];

    const int tid  = threadIdx.x;
    const int w    = tid >> 5;
    const int lane = tid & 31;
    const int col  = blockIdx.x * 2 + w;
    const int b    = col >> 8;
    const int c    = col & (CC - 1);

    if (tid == 0) s_nfail = 0;
    __syncthreads();

    // counts + exclusive scan over 8 chunks (lanes 0..7)
    int cnt = (lane < CH) ? g_cnt[col * CH + lane] : 0;
    unsigned int ovf = __ballot_sync(0xffffffffu, (lane < CH) && (cnt > CHCAP));
    int sc = cnt;
#pragma unroll
    for (int d = 1; d < 8; d <<= 1) {
        int t2 = __shfl_up_sync(0xffffffffu, sc, d);
        if (lane >= d) sc += t2;
    }
    const int n = __shfl_sync(0xffffffffu, sc, CH - 1);
    const int excl = sc - cnt;

    if (n >= KK && n <= NSEL && ovf == 0u) {
        // ---- compact chunk segments into smem ----
#pragma unroll
        for (int h = 0; h < CH; h++) {
            int chn = __shfl_sync(0xffffffffu, cnt, h);
            int bs  = __shfl_sync(0xffffffffu, excl, h);
            const unsigned long long* src = &g_cand[((size_t)col * CH + h) * CHCAP];
            for (int i = lane; i < chn; i += 32)
                sbuf[w][bs + i] = src[i];
        }
        __syncwarp();

        unsigned long long t_lo, t_hi;      // top-64 multiset (order-free)

        if (n <= 128) {
            // two 64-runs (ILP=2) + one half-cleaner
            unsigned long long lo[2], hi[2];
#pragma unroll
            for (int q = 0; q < 2; q++) {
                int e0 = q * 64 + lane;
                int e1 = q * 64 + 32 + lane;
                lo[q] = (e0 < n) ? sbuf[w][e0] : 0ull;
                hi[q] = (e1 < n) ? sbuf[w][e1] : 0ull;
            }
            sort64_batch<2>(lo, hi, lane);
            t_lo = max64(lo[0], __shfl_xor_sync(0xffffffffu, hi[1], 31));
            t_hi = max64(hi[0], __shfl_xor_sync(0xffffffffu, lo[1], 31));
        } else {
            // four 64-runs (ILP=4) + tournament of half-cleaners
            unsigned long long lo[4], hi[4];
#pragma unroll
            for (int q = 0; q < 4; q++) {
                int e0 = q * 64 + lane;
                int e1 = q * 64 + 32 + lane;
                lo[q] = (e0 < n) ? sbuf[w][e0] : 0ull;
                hi[q] = (e1 < n) ? sbuf[w][e1] : 0ull;
            }
            sort64_batch<4>(lo, hi, lane);
            // top-64(S0,S1) sorted
            unsigned long long m_lo = max64(lo[0], __shfl_xor_sync(0xffffffffu, hi[1], 31));
            unsigned long long m_hi = max64(hi[0], __shfl_xor_sync(0xffffffffu, lo[1], 31));
            bmerge64(m_lo, m_hi, lane);
            // top-64(S2,S3) sorted
            unsigned long long p_lo = max64(lo[2], __shfl_xor_sync(0xffffffffu, hi[3], 31));
            unsigned long long p_hi = max64(hi[2], __shfl_xor_sync(0xffffffffu, lo[3], 31));
            bmerge64(p_lo, p_hi, lane);
            // final half-cleaner (multiset only)
            t_lo = max64(m_lo, __shfl_xor_sync(0xffffffffu, p_hi, 31));
            t_hi = max64(m_hi, __shfl_xor_sync(0xffffffffu, p_lo, 31));
        }

        // ---- index order: 32-bit token sort (s<<7 | pos), s distinct ----
        unsigned int tok0 = (((unsigned int)t_lo & 0x1FFFu) << 7) | (unsigned int)lane;
        unsigned int tok1 = (((unsigned int)t_hi & 0x1FFFu) << 7) | (unsigned int)(32 + lane);
        sort64_u32(tok0, tok1, lane);

        // ---- gather keys by pos and write out[b][f][c] ----
        unsigned int klo = (unsigned int)(t_lo >> 32);
        unsigned int khi = (unsigned int)(t_hi >> 32);

        int p0 = tok0 & 127;
        unsigned int g0a = __shfl_sync(0xffffffffu, klo, p0 & 31);
        unsigned int g0b = __shfl_sync(0xffffffffu, khi, p0 & 31);
        unsigned int key0 = (p0 < 32) ? g0a : g0b;

        int p1 = tok1 & 127;
        unsigned int g1a = __shfl_sync(0xffffffffu, klo, p1 & 31);
        unsigned int g1b = __shfl_sync(0xffffffffu, khi, p1 & 31);
        unsigned int key1 = (p1 < 32) ? g1a : g1b;

        out[((size_t)b * KK + lane) * CC + c]      = __uint_as_float(key0 & 0x7FFFFFFFu);
        out[((size_t)b * KK + 32 + lane) * CC + c] = __uint_as_float(key1 & 0x7FFFFFFFu);
    } else {
        if (lane == 0) {
            int i = atomicAdd(&s_nfail, 1);
            s_fail[i] = col;
        }
    }

    // ---- block-cooperative exact epilogue (expected no-op; sigma>=5 events) ----
    __syncthreads();
    const int nf = s_nfail;
    for (int f = 0; f < nf; f++) {
        const int fcol = s_fail[f];
        const int fb = fcol >> 8;
        const int fc = fcol & (CC - 1);
        const size_t xbase = (size_t)fb * SS * CC + fc;

        unsigned long long V = 0;
        for (int bit = 63; bit >= 0; bit--) {
            unsigned long long cand = V | (1ull << bit);
            int local = 0;
            for (int s = tid; s < SS; s += 64) {
                float fv = x[xbase + (size_t)s * CC];
                unsigned long long comp =
                    ((unsigned long long)fkey(fv) << 32) | (unsigned int)s;
                local += (comp >= cand);
            }
            sred[tid] = local;
            __syncthreads();
            for (int st = 32; st > 0; st >>= 1) {
                if (tid < st) sred[tid] += sred[tid + st];
                __syncthreads();
            }
            int cntv = sred[0];
            __syncthreads();
            if (cntv >= KK) V = cand;
        }

        const int per = SS / 64;            // 128
        int lcnt = 0;
        for (int k2 = 0; k2 < per; k2++) {
            int s = tid * per + k2;
            float fv = x[xbase + (size_t)s * CC];
            unsigned long long comp =
                ((unsigned long long)fkey(fv) << 32) | (unsigned int)s;
            lcnt += (comp >= V);
        }
        sred[tid] = lcnt;
        __syncthreads();
        for (int off = 1; off < 64; off <<= 1) {
            int vv = sred[tid];
            int ww = (tid >= off) ? sred[tid - off] : 0;
            __syncthreads();
            sred[tid] = vv + ww;
            __syncthreads();
        }
        int basep = sred[tid] - lcnt;
        for (int k2 = 0; k2 < per; k2++) {
            int s = tid * per + k2;
            float fv = x[xbase + (size_t)s * CC];
            unsigned long long comp =
                ((unsigned long long)fkey(fv) << 32) | (unsigned int)s;
            if (comp >= V) {
                if (basep < KK)
                    out[((size_t)fb * KK + basep) * CC + fc] = fv;
                basep++;
            }
        }
        __syncthreads();
    }
}

extern "C" void kernel_launch(void* const* d_in, const int* in_sizes, int n_in,
                              void* d_out, int out_size) {
    const float* x = (const float*)d_in[0];
    float* out = (float*)d_out;

    stream_kernel<<<BB * 16 * CH, 256>>>(x);     // 4096 blocks
    select_kernel<<<NCOL / 2, 64>>>(x, out);     // 4096 blocks
}